// round 4
// baseline (speedup 1.0000x reference)
#include <cuda_runtime.h>
#include <math.h>

#define NCTA 128
#define TPB  256
#define XSTF 132             // dup row: 128 floats + 4 pad (33x16B, odd -> conflict-free)
#define XBUF (64 * XSTF)

// ---------------- device scratch ----------------
__device__ float g_Wr[3072 * 2048];      // reordered recurrent weights: enc0(512)|enc1(1024)|dec0(512)|dec1(1024)
__device__ float g_h0[2 * 64 * 512];
__device__ float g_h1[2 * 64 * 512];
__device__ float g_c0[64 * 512];
__device__ float g_c1[64 * 512];
__device__ float g_en_last[64 * 512];
__device__ float g_embz_enc[128 * 2048]; // emb@encW0[0:256]+encb0, reordered cols
__device__ float g_embz_dec[128 * 2048]; // emb@decW0[0:256]+decb0, reordered cols
__device__ float g_enlz[64 * 2048];      // en_last@decW0[256:768], reordered cols
__device__ float g_dec_out[64 * 256 * 512];
__device__ unsigned g_bar;

__device__ __forceinline__ float sigmoidf_(float x) { return 1.0f / (1.0f + __expf(-x)); }

__device__ __forceinline__ void grid_bar(unsigned target) {
    __syncthreads();
    if (threadIdx.x == 0) {
        __threadfence();
        atomicAdd(&g_bar, 1u);
        unsigned v;
        do {
            asm volatile("ld.acquire.gpu.u32 %0, [%1];" : "=r"(v) : "l"(&g_bar));
        } while (v < target);
    }
    __syncthreads();
}

// 64 k's: 32 LDS.128 (dup-x) + 64 LDS.128 (w) + 128 FFMA2
__device__ __forceinline__ void compute_chunk2(const float* __restrict__ xrow,
                                               const ulonglong2* __restrict__ wb,
                                               unsigned long long& a01,
                                               unsigned long long& a23) {
    const ulonglong2* xd = reinterpret_cast<const ulonglong2*>(xrow);
#pragma unroll
    for (int kk = 0; kk < 64; kk += 2) {
        ulonglong2 x2 = xd[kk >> 1];          // ((x_k,x_k),(x_{k+1},x_{k+1}))
        ulonglong2 w0 = wb[kk * 4];           // k   : cols (ul*4+0,1 | 2,3)
        ulonglong2 w1 = wb[kk * 4 + 4];       // k+1
        asm("fma.rn.f32x2 %0, %1, %2, %0;" : "+l"(a01) : "l"(x2.x), "l"(w0.x));
        asm("fma.rn.f32x2 %0, %1, %2, %0;" : "+l"(a23) : "l"(x2.x), "l"(w0.y));
        asm("fma.rn.f32x2 %0, %1, %2, %0;" : "+l"(a01) : "l"(x2.y), "l"(w1.x));
        asm("fma.rn.f32x2 %0, %1, %2, %0;" : "+l"(a23) : "l"(x2.y), "l"(w1.y));
    }
}

__device__ __forceinline__ void load4cg(const float* __restrict__ src, int fr, int fqb, float4* v) {
    const float4* p = reinterpret_cast<const float4*>(src + fr * 512);
#pragma unroll
    for (int j = 0; j < 4; ++j) v[j] = __ldcg(p + fqb + j);
}

__device__ __forceinline__ void fill_dup(float* __restrict__ xb, int fr, int fqb, const float4* v) {
    float4* row = reinterpret_cast<float4*>(xb + fr * XSTF);
#pragma unroll
    for (int j = 0; j < 4; ++j) {
        float4 a = v[j];
        row[(fqb + j) * 2]     = make_float4(a.x, a.x, a.y, a.y);
        row[(fqb + j) * 2 + 1] = make_float4(a.z, a.z, a.w, a.w);
    }
}

// ---------------- init / reorder ----------------
__global__ void init_kernel() {
    int idx = blockIdx.x * blockDim.x + threadIdx.x;
    int stride = gridDim.x * blockDim.x;
    for (int i = idx; i < 2 * 64 * 512; i += stride) { g_h0[i] = 0.f; g_h1[i] = 0.f; }
    if (idx == 0) g_bar = 0u;
}

// dst slab layout per CTA: [k][16], r = ul*4 + g ; orig col = g*512 + (cta*4+ul)
__global__ void reorder_kernel(const float* __restrict__ src, size_t dst_off, int K) {
    size_t n = (size_t)K * 2048;
    float* dst = g_Wr + dst_off;
    int slab = K * 16;
    for (size_t idx = (size_t)blockIdx.x * blockDim.x + threadIdx.x; idx < n;
         idx += (size_t)gridDim.x * blockDim.x) {
        int ublk = (int)(idx / slab);
        int rem  = (int)(idx - (size_t)ublk * slab);
        int k = rem >> 4;
        int r = rem & 15;
        dst[idx] = src[(size_t)k * 2048 + (size_t)(r & 3) * 512 + ublk * 4 + (r >> 2)];
    }
}

// ---------------- precompute GEMM: C[M,2048] = A[M,K] @ B[K,2048] (+bias), reordered col store ----
__global__ void __launch_bounds__(TPB, 1) gemm_pre(
    const float* __restrict__ A, int M, int K,
    const float* __restrict__ B, const float* __restrict__ bias,
    float* __restrict__ C)
{
    const int col0 = blockIdx.x * 128;
    __shared__ __align__(16) float As[128][33];
    __shared__ __align__(16) float Ws[32][128];
    const int tid = threadIdx.x;
    const int tc = tid & 31, rg = tid >> 5;

    float4 acc[16];
#pragma unroll
    for (int i = 0; i < 16; i++) acc[i] = make_float4(0.f, 0.f, 0.f, 0.f);

    for (int k0 = 0; k0 < K; k0 += 32) {
        for (int e = tid; e < 128 * 32; e += TPB) {
            int r = e >> 5, kk = e & 31;
            As[r][kk] = (r < M) ? A[(size_t)r * K + k0 + kk] : 0.f;
        }
        for (int e = tid; e < 32 * 128; e += TPB) {
            int kk = e >> 7, c = e & 127;
            Ws[kk][c] = B[(size_t)(k0 + kk) * 2048 + col0 + c];
        }
        __syncthreads();
#pragma unroll
        for (int kk = 0; kk < 32; kk++) {
            float4 w = *reinterpret_cast<const float4*>(&Ws[kk][tc * 4]);
#pragma unroll
            for (int r = 0; r < 16; r++) {
                float a = As[rg * 16 + r][kk];
                acc[r].x = fmaf(a, w.x, acc[r].x);
                acc[r].y = fmaf(a, w.y, acc[r].y);
                acc[r].z = fmaf(a, w.z, acc[r].z);
                acc[r].w = fmaf(a, w.w, acc[r].w);
            }
        }
        __syncthreads();
    }
#pragma unroll
    for (int r = 0; r < 16; r++) {
        int row = rg * 16 + r;
        if (row >= M) continue;
        float av[4] = {acc[r].x, acc[r].y, acc[r].z, acc[r].w};
#pragma unroll
        for (int q = 0; q < 4; q++) {
            int oc = col0 + tc * 4 + q;
            float val = av[q] + (bias ? bias[oc] : 0.f);
            int g = oc >> 9, u = oc & 511;
            int nc = (u >> 2) * 16 + (u & 3) * 4 + g;
            C[(size_t)row * 2048 + nc] = val;
        }
    }
}

// ---------------- encoder ----------------
__global__ void __launch_bounds__(TPB, 1) encoder_kernel(
    const int* __restrict__ en_input, const int* __restrict__ en_len,
    const float* __restrict__ b1g)
{
    extern __shared__ float sm[];
    float* ws0 = sm;                 // 512*16
    float* ws1 = sm + 512 * 16;      // 1024*16
    float* xs  = sm + 1536 * 16;     // 2 * XBUF

    const int cta = blockIdx.x, tid = threadIdx.x;
    const int m = tid >> 2, ul = tid & 3;
    const int unit = cta * 4 + ul;
    const int fqb = (tid & 3) * 4;   // fill: row m, float4 quads fqb..fqb+3

    // preload weights
    {
        const float4* w0g = (const float4*)(g_Wr) + (size_t)cta * (512 * 4);
        float4* s0 = (float4*)ws0;
        for (int i = tid; i < 512 * 4; i += TPB) s0[i] = w0g[i];
        const float4* w1g = (const float4*)(g_Wr + (size_t)512 * 2048) + (size_t)cta * (1024 * 4);
        float4* s1 = (float4*)ws1;
        for (int i = tid; i < 1024 * 4; i += TPB) s1[i] = w1g[i];
    }
    // layer-1 bias packed
    unsigned long long b01, b23;
    {
        union { float2 f; unsigned long long u; } p0, p1;
        p0.f = make_float2(b1g[0 * 512 + unit], b1g[1 * 512 + unit]);
        p1.f = make_float2(b1g[2 * 512 + unit], b1g[3 * 512 + unit]);
        b01 = p0.u; b23 = p1.u;
    }
    const int mylen = en_len[m];
    const ulonglong2* wb0 = reinterpret_cast<const ulonglong2*>(ws0) + ul;
    const ulonglong2* wb1 = reinterpret_cast<const ulonglong2*>(ws1) + ul;

    float c0 = 0.f, c1v = 0.f, h0r = 0.f, h1r = 0.f;
    __syncthreads();

    for (int t = 0; t < 256; ++t) {
        const float* h0prev = g_h0 + ((t + 1) & 1) * (64 * 512);
        float*       h0cur  = g_h0 + (t & 1) * (64 * 512);
        const float* h1prev = g_h1 + ((t + 1) & 1) * (64 * 512);
        float*       h1cur  = g_h1 + (t & 1) * (64 * 512);

        int tok = en_input[m * 256 + t];
        ulonglong2 ez = *reinterpret_cast<const ulonglong2*>(
            g_embz_enc + (size_t)tok * 2048 + cta * 16 + ul * 4);

        unsigned long long a01 = 0, a23 = 0;
        // ---- layer 0: K=512 (h0prev), 8 chunks ----
        {
            float4 v[4];
            load4cg(h0prev, m, fqb, v);
            fill_dup(xs, m, fqb, v);
            int buf = 0;
            for (int ch = 0; ch < 8; ++ch) {
                float4 nv[4];
                if (ch + 1 < 8) load4cg(h0prev + (ch + 1) * 64, m, fqb, nv);
                __syncthreads();
                compute_chunk2(xs + buf * XBUF + m * XSTF, wb0 + ch * 256, a01, a23);
                if (ch + 1 < 8) fill_dup(xs + (buf ^ 1) * XBUF, m, fqb, nv);
                buf ^= 1;
            }
        }
        asm("add.rn.f32x2 %0, %0, %1;" : "+l"(a01) : "l"(ez.x));
        asm("add.rn.f32x2 %0, %0, %1;" : "+l"(a23) : "l"(ez.y));
        {
            bool valid = t < mylen;
            union { unsigned long long u; float2 f; } u01, u23;
            u01.u = a01; u23.u = a23;
            float nc = c0 * sigmoidf_(u23.f.x + 1.0f) + sigmoidf_(u01.f.x) * tanhf(u01.f.y);
            float nh = tanhf(nc) * sigmoidf_(u23.f.y);
            if (valid) { c0 = nc; h0r = nh; }
            h0cur[m * 512 + unit] = h0r;
        }
        grid_bar((unsigned)(t + 1) * NCTA);

        // ---- layer 1: K=1024 (h0cur | h1prev), 16 chunks ----
        a01 = 0; a23 = 0;
        {
            float4 v[4];
            load4cg(h0cur, m, fqb, v);
            fill_dup(xs, m, fqb, v);
            int buf = 0;
            for (int ch = 0; ch < 16; ++ch) {
                float4 nv[4];
                if (ch + 1 < 16) {
                    int cn = ch + 1;
                    const float* hp = (cn < 8) ? (h0cur + cn * 64) : (h1prev + (cn - 8) * 64);
                    load4cg(hp, m, fqb, nv);
                }
                __syncthreads();
                compute_chunk2(xs + buf * XBUF + m * XSTF, wb1 + ch * 256, a01, a23);
                if (ch + 1 < 16) fill_dup(xs + (buf ^ 1) * XBUF, m, fqb, nv);
                buf ^= 1;
            }
        }
        __syncthreads();
        asm("add.rn.f32x2 %0, %0, %1;" : "+l"(a01) : "l"(b01));
        asm("add.rn.f32x2 %0, %0, %1;" : "+l"(a23) : "l"(b23));
        {
            bool valid = t < mylen;
            union { unsigned long long u; float2 f; } u01, u23;
            u01.u = a01; u23.u = a23;
            float nc = c1v * sigmoidf_(u23.f.x + 1.0f) + sigmoidf_(u01.f.x) * tanhf(u01.f.y);
            float nh = tanhf(nc) * sigmoidf_(u23.f.y);
            if (valid) { c1v = nc; h1r = nh; g_en_last[m * 512 + unit] = nh; }
            h1cur[m * 512 + unit] = h1r;
        }
    }
    g_c0[m * 512 + unit] = c0;
    g_c1[m * 512 + unit] = c1v;
}

// ---------------- decoder ----------------
__global__ void __launch_bounds__(TPB, 1) decoder_kernel(
    const int* __restrict__ dec_input, const int* __restrict__ dec_len,
    const float* __restrict__ b1g)
{
    extern __shared__ float sm[];
    float* ws0 = sm;                 // 512*16
    float* ws1 = sm + 512 * 16;      // 1024*16
    float* xs  = sm + 1536 * 16;

    const int cta = blockIdx.x, tid = threadIdx.x;
    const int m = tid >> 2, ul = tid & 3;
    const int unit = cta * 4 + ul;
    const int fqb = (tid & 3) * 4;

    {
        const float4* w0g = (const float4*)(g_Wr + (size_t)1536 * 2048) + (size_t)cta * (512 * 4);
        float4* s0 = (float4*)ws0;
        for (int i = tid; i < 512 * 4; i += TPB) s0[i] = w0g[i];
        const float4* w1g = (const float4*)(g_Wr + (size_t)2048 * 2048) + (size_t)cta * (1024 * 4);
        float4* s1 = (float4*)ws1;
        for (int i = tid; i < 1024 * 4; i += TPB) s1[i] = w1g[i];
    }
    unsigned long long b01, b23;
    {
        union { float2 f; unsigned long long u; } p0, p1;
        p0.f = make_float2(b1g[0 * 512 + unit], b1g[1 * 512 + unit]);
        p1.f = make_float2(b1g[2 * 512 + unit], b1g[3 * 512 + unit]);
        b01 = p0.u; b23 = p1.u;
    }
    const int mylen = dec_len[m];
    // constant en_last contribution (already includes no bias; decb0 folded in embz_dec)
    ulonglong2 el = *reinterpret_cast<const ulonglong2*>(
        g_enlz + (size_t)m * 2048 + cta * 16 + ul * 4);

    const ulonglong2* wb0 = reinterpret_cast<const ulonglong2*>(ws0) + ul;
    const ulonglong2* wb1 = reinterpret_cast<const ulonglong2*>(ws1) + ul;

    float c0 = g_c0[m * 512 + unit];
    float c1v = g_c1[m * 512 + unit];
    float h0r = g_h0[64 * 512 + m * 512 + unit];   // encoder t=255 wrote buffer 1
    float h1r = g_h1[64 * 512 + m * 512 + unit];
    __syncthreads();

    for (int t = 0; t < 256; ++t) {
        const float* h0prev = g_h0 + ((t + 1) & 1) * (64 * 512);
        float*       h0cur  = g_h0 + (t & 1) * (64 * 512);
        const float* h1prev = g_h1 + ((t + 1) & 1) * (64 * 512);
        float*       h1cur  = g_h1 + (t & 1) * (64 * 512);

        int tok = dec_input[m * 256 + t];
        ulonglong2 ez = *reinterpret_cast<const ulonglong2*>(
            g_embz_dec + (size_t)tok * 2048 + cta * 16 + ul * 4);

        unsigned long long a01 = 0, a23 = 0;
        // ---- layer 0: K=512 (h0prev), 8 chunks ----
        {
            float4 v[4];
            load4cg(h0prev, m, fqb, v);
            fill_dup(xs, m, fqb, v);
            int buf = 0;
            for (int ch = 0; ch < 8; ++ch) {
                float4 nv[4];
                if (ch + 1 < 8) load4cg(h0prev + (ch + 1) * 64, m, fqb, nv);
                __syncthreads();
                compute_chunk2(xs + buf * XBUF + m * XSTF, wb0 + ch * 256, a01, a23);
                if (ch + 1 < 8) fill_dup(xs + (buf ^ 1) * XBUF, m, fqb, nv);
                buf ^= 1;
            }
        }
        asm("add.rn.f32x2 %0, %0, %1;" : "+l"(a01) : "l"(ez.x));
        asm("add.rn.f32x2 %0, %0, %1;" : "+l"(a23) : "l"(ez.y));
        asm("add.rn.f32x2 %0, %0, %1;" : "+l"(a01) : "l"(el.x));
        asm("add.rn.f32x2 %0, %0, %1;" : "+l"(a23) : "l"(el.y));
        {
            bool valid = t < mylen;
            union { unsigned long long u; float2 f; } u01, u23;
            u01.u = a01; u23.u = a23;
            float nc = c0 * sigmoidf_(u23.f.x + 1.0f) + sigmoidf_(u01.f.x) * tanhf(u01.f.y);
            float nh = tanhf(nc) * sigmoidf_(u23.f.y);
            if (valid) { c0 = nc; h0r = nh; }
            h0cur[m * 512 + unit] = h0r;
        }
        grid_bar((unsigned)(256 + t + 1) * NCTA);

        // ---- layer 1: K=1024, 16 chunks ----
        a01 = 0; a23 = 0;
        {
            float4 v[4];
            load4cg(h0cur, m, fqb, v);
            fill_dup(xs, m, fqb, v);
            int buf = 0;
            for (int ch = 0; ch < 16; ++ch) {
                float4 nv[4];
                if (ch + 1 < 16) {
                    int cn = ch + 1;
                    const float* hp = (cn < 8) ? (h0cur + cn * 64) : (h1prev + (cn - 8) * 64);
                    load4cg(hp, m, fqb, nv);
                }
                __syncthreads();
                compute_chunk2(xs + buf * XBUF + m * XSTF, wb1 + ch * 256, a01, a23);
                if (ch + 1 < 16) fill_dup(xs + (buf ^ 1) * XBUF, m, fqb, nv);
                buf ^= 1;
            }
        }
        __syncthreads();
        asm("add.rn.f32x2 %0, %0, %1;" : "+l"(a01) : "l"(b01));
        asm("add.rn.f32x2 %0, %0, %1;" : "+l"(a23) : "l"(b23));
        {
            bool valid = t < mylen;
            union { unsigned long long u; float2 f; } u01, u23;
            u01.u = a01; u23.u = a23;
            float nc = c1v * sigmoidf_(u23.f.x + 1.0f) + sigmoidf_(u01.f.x) * tanhf(u01.f.y);
            float nh = tanhf(nc) * sigmoidf_(u23.f.y);
            if (valid) { c1v = nc; h1r = nh; }
            h1cur[m * 512 + unit] = h1r;
            g_dec_out[((size_t)m * 256 + t) * 512 + unit] = valid ? h1r : 0.f;
        }
    }
}

// ---------------- projection: [16384,512] @ [512,128] + bias ----------------
__global__ void __launch_bounds__(TPB, 1) proj_kernel(
    const float* __restrict__ projW, const float* __restrict__ projb,
    float* __restrict__ out)
{
    const int row0 = blockIdx.x * 128;
    __shared__ __align__(16) float As[128][33];
    __shared__ __align__(16) float Ws[32][128];
    const int tid = threadIdx.x;
    const int tc = tid & 31, rg = tid >> 5;

    float4 acc[16];
#pragma unroll
    for (int i = 0; i < 16; i++) acc[i] = make_float4(0.f, 0.f, 0.f, 0.f);

    for (int k0 = 0; k0 < 512; k0 += 32) {
        for (int e = tid; e < 128 * 32; e += TPB) {
            int r = e >> 5, kk = e & 31;
            As[r][kk] = g_dec_out[(size_t)(row0 + r) * 512 + k0 + kk];
        }
        for (int e = tid; e < 32 * 128; e += TPB) {
            int kk = e >> 7, c = e & 127;
            Ws[kk][c] = projW[(size_t)(k0 + kk) * 128 + c];
        }
        __syncthreads();
#pragma unroll
        for (int kk = 0; kk < 32; kk++) {
            float4 w = *reinterpret_cast<const float4*>(&Ws[kk][tc * 4]);
#pragma unroll
            for (int r = 0; r < 16; r++) {
                float a = As[rg * 16 + r][kk];
                acc[r].x = fmaf(a, w.x, acc[r].x);
                acc[r].y = fmaf(a, w.y, acc[r].y);
                acc[r].z = fmaf(a, w.z, acc[r].z);
                acc[r].w = fmaf(a, w.w, acc[r].w);
            }
        }
        __syncthreads();
    }
    float4 pb = *reinterpret_cast<const float4*>(&projb[tc * 4]);
#pragma unroll
    for (int r = 0; r < 16; r++) {
        int row = row0 + rg * 16 + r;
        float4 v = make_float4(acc[r].x + pb.x, acc[r].y + pb.y,
                               acc[r].z + pb.z, acc[r].w + pb.w);
        *reinterpret_cast<float4*>(&out[(size_t)row * 128 + tc * 4]) = v;
    }
}

// ---------------- launch ----------------
#define SEQ_SMEM ((1536 * 16 + 2 * XBUF) * 4)

extern "C" void kernel_launch(void* const* d_in, const int* in_sizes, int n_in,
                              void* d_out, int out_size) {
    const int*   en_input  = (const int*)d_in[0];
    const int*   en_len    = (const int*)d_in[1];
    const int*   dec_input = (const int*)d_in[2];
    const int*   dec_len   = (const int*)d_in[3];
    const float* embed     = (const float*)d_in[4];
    const float* encW0     = (const float*)d_in[5];
    const float* encb0     = (const float*)d_in[6];
    const float* encW1     = (const float*)d_in[7];
    const float* encb1     = (const float*)d_in[8];
    const float* decW0     = (const float*)d_in[9];
    const float* decb0     = (const float*)d_in[10];
    const float* decW1     = (const float*)d_in[11];
    const float* decb1     = (const float*)d_in[12];
    const float* projW     = (const float*)d_in[13];
    const float* projb     = (const float*)d_in[14];
    float* out = (float*)d_out;

    float* embz_enc; cudaGetSymbolAddress((void**)&embz_enc, g_embz_enc);
    float* embz_dec; cudaGetSymbolAddress((void**)&embz_dec, g_embz_dec);
    float* enlz;     cudaGetSymbolAddress((void**)&enlz, g_enlz);
    float* en_last;  cudaGetSymbolAddress((void**)&en_last, g_en_last);

    cudaFuncSetAttribute(encoder_kernel, cudaFuncAttributeMaxDynamicSharedMemorySize, SEQ_SMEM);
    cudaFuncSetAttribute(decoder_kernel, cudaFuncAttributeMaxDynamicSharedMemorySize, SEQ_SMEM);

    init_kernel<<<128, 256>>>();
    // recurrent-weight slabs (h-parts only)
    reorder_kernel<<<512, 256>>>(encW0 + (size_t)256 * 2048, (size_t)0,           512);
    reorder_kernel<<<512, 256>>>(encW1,                      (size_t)512  * 2048, 1024);
    reorder_kernel<<<512, 256>>>(decW0 + (size_t)768 * 2048, (size_t)1536 * 2048, 512);
    reorder_kernel<<<512, 256>>>(decW1,                      (size_t)2048 * 2048, 1024);
    // token tables (fold biases of layer 0)
    gemm_pre<<<16, TPB>>>(embed, 128, 256, encW0, encb0, embz_enc);
    gemm_pre<<<16, TPB>>>(embed, 128, 256, decW0, decb0, embz_dec);

    encoder_kernel<<<NCTA, TPB, SEQ_SMEM>>>(en_input, en_len, encb1);

    // en_last @ decW0[256:768] (constant over all decoder steps)
    gemm_pre<<<16, TPB>>>(en_last, 64, 512, decW0 + (size_t)256 * 2048, (const float*)nullptr, enlz);

    decoder_kernel<<<NCTA, TPB, SEQ_SMEM>>>(dec_input, dec_len, decb1);
    proj_kernel<<<128, TPB>>>(projW, projb, out);
}

// round 5
// speedup vs baseline: 1.1389x; 1.1389x over previous
#include <cuda_runtime.h>
#include <math.h>

#define NCTA 128
#define TPB  512
#define XSTF 132             // xs row stride in floats (33x16B, odd -> conflict-free)
#define XBUF (64 * XSTF)     // one buffer: 64 rows x 128 floats (+pad)

// ---------------- device scratch ----------------
__device__ float g_Wr[3072 * 2048];      // reordered recurrent weights: enc0(512)|enc1(1024)|dec0(512)|dec1(1024)
__device__ float g_h0[2 * 64 * 512];
__device__ float g_h1[2 * 64 * 512];
__device__ float g_c0[64 * 512];
__device__ float g_c1[64 * 512];
__device__ float g_en_last[64 * 512];
__device__ float g_embz_enc[128 * 2048]; // emb@encW0[0:256]+encb0, reordered cols
__device__ float g_embz_dec[128 * 2048]; // emb@decW0[0:256]+decb0, reordered cols
__device__ float g_enlz[64 * 2048];      // en_last@decW0[256:768], reordered cols
__device__ float g_dec_out[64 * 256 * 512];
__device__ unsigned g_bar;

__device__ __forceinline__ float sigmoidf_(float x) { return 1.0f / (1.0f + __expf(-x)); }

__device__ __forceinline__ void grid_bar(unsigned target) {
    __syncthreads();
    if (threadIdx.x == 0) {
        __threadfence();
        atomicAdd(&g_bar, 1u);
        unsigned v;
        do {
            asm volatile("ld.acquire.gpu.u32 %0, [%1];" : "=r"(v) : "l"(&g_bar));
        } while (v < target);
    }
    __syncthreads();
}

// 128 k's: per thread 32 LDS.128 (x) + 128 LDS.64 (w) + 256 FFMA
__device__ __forceinline__ void compute_chunk(const float* __restrict__ xrow,
                                              const float2* __restrict__ w2,
                                              float2& acc) {
    const float4* xr = reinterpret_cast<const float4*>(xrow);
#pragma unroll
    for (int kq = 0; kq < 32; ++kq) {
        float4 xv = xr[kq];
        float xa[4] = {xv.x, xv.y, xv.z, xv.w};
#pragma unroll
        for (int q = 0; q < 4; ++q) {
            float2 w = w2[(kq * 4 + q) * 8];
            acc.x = fmaf(xa[q], w.x, acc.x);
            acc.y = fmaf(xa[q], w.y, acc.y);
        }
    }
}

// fill one 128-k chunk of xs from a global h region (row-major, 512-float rows)
__device__ __forceinline__ void load4cg(const float* __restrict__ hp, int fr, int qb, float4* v) {
    const float4* p = reinterpret_cast<const float4*>(hp + fr * 512);
#pragma unroll
    for (int j = 0; j < 4; ++j) v[j] = __ldcg(p + qb + j);
}

__device__ __forceinline__ void fill_x(float* __restrict__ xb, int fr, int qb, const float4* v) {
    float4* row = reinterpret_cast<float4*>(xb + fr * XSTF);
#pragma unroll
    for (int j = 0; j < 4; ++j) row[qb + j] = v[j];
}

// ---------------- init / reorder ----------------
__global__ void init_kernel() {
    int idx = blockIdx.x * blockDim.x + threadIdx.x;
    int stride = gridDim.x * blockDim.x;
    for (int i = idx; i < 2 * 64 * 512; i += stride) { g_h0[i] = 0.f; g_h1[i] = 0.f; }
    if (idx == 0) g_bar = 0u;
}

// dst slab layout per CTA: [k][16], r = ul*4 + g ; orig col = g*512 + (cta*4+ul)
__global__ void reorder_kernel(const float* __restrict__ src, size_t dst_off, int K) {
    size_t n = (size_t)K * 2048;
    float* dst = g_Wr + dst_off;
    int slab = K * 16;
    for (size_t idx = (size_t)blockIdx.x * blockDim.x + threadIdx.x; idx < n;
         idx += (size_t)gridDim.x * blockDim.x) {
        int ublk = (int)(idx / slab);
        int rem  = (int)(idx - (size_t)ublk * slab);
        int k = rem >> 4;
        int r = rem & 15;
        dst[idx] = src[(size_t)k * 2048 + (size_t)(r & 3) * 512 + ublk * 4 + (r >> 2)];
    }
}

// ---------------- precompute GEMM: C[M,2048] = A[M,K] @ B[K,2048] (+bias), reordered col store ----
__global__ void __launch_bounds__(256, 1) gemm_pre(
    const float* __restrict__ A, int M, int K,
    const float* __restrict__ B, const float* __restrict__ bias,
    float* __restrict__ C)
{
    const int col0 = blockIdx.x * 128;
    __shared__ __align__(16) float As[128][33];
    __shared__ __align__(16) float Ws[32][128];
    const int tid = threadIdx.x;
    const int tc = tid & 31, rg = tid >> 5;

    float4 acc[16];
#pragma unroll
    for (int i = 0; i < 16; i++) acc[i] = make_float4(0.f, 0.f, 0.f, 0.f);

    for (int k0 = 0; k0 < K; k0 += 32) {
        for (int e = tid; e < 128 * 32; e += 256) {
            int r = e >> 5, kk = e & 31;
            As[r][kk] = (r < M) ? A[(size_t)r * K + k0 + kk] : 0.f;
        }
        for (int e = tid; e < 32 * 128; e += 256) {
            int kk = e >> 7, c = e & 127;
            Ws[kk][c] = B[(size_t)(k0 + kk) * 2048 + col0 + c];
        }
        __syncthreads();
#pragma unroll
        for (int kk = 0; kk < 32; kk++) {
            float4 w = *reinterpret_cast<const float4*>(&Ws[kk][tc * 4]);
#pragma unroll
            for (int r = 0; r < 16; r++) {
                float a = As[rg * 16 + r][kk];
                acc[r].x = fmaf(a, w.x, acc[r].x);
                acc[r].y = fmaf(a, w.y, acc[r].y);
                acc[r].z = fmaf(a, w.z, acc[r].z);
                acc[r].w = fmaf(a, w.w, acc[r].w);
            }
        }
        __syncthreads();
    }
#pragma unroll
    for (int r = 0; r < 16; r++) {
        int row = rg * 16 + r;
        if (row >= M) continue;
        float av[4] = {acc[r].x, acc[r].y, acc[r].z, acc[r].w};
#pragma unroll
        for (int q = 0; q < 4; q++) {
            int oc = col0 + tc * 4 + q;
            float val = av[q] + (bias ? bias[oc] : 0.f);
            int g = oc >> 9, u = oc & 511;
            int nc = (u >> 2) * 16 + (u & 3) * 4 + g;
            C[(size_t)row * 2048 + nc] = val;
        }
    }
}

// ================= persistent sequence kernels =================
// thread map: m = tid>>3 (batch row), cp = tid&7 (ul = cp>>1, gp = cp&1)
// acc.xy = gates (2gp, 2gp+1) of unit (cta*4+ul)
// fill map: fr = tid>>3 (row), qb = (tid&7)*4 (float4 quads qb..qb+3)

struct GateOut { float nc, nh; };
__device__ __forceinline__ GateOut lstm_gates(float2 acc, int gp, float c) {
    float ox = __shfl_xor_sync(0xffffffffu, acc.x, 1);
    float oy = __shfl_xor_sync(0xffffffffu, acc.y, 1);
    float zi, zj, zf, zo;
    if (gp == 0) { zi = acc.x; zj = acc.y; zf = ox;    zo = oy;    }
    else         { zi = ox;    zj = oy;    zf = acc.x; zo = acc.y; }
    GateOut r;
    r.nc = c * sigmoidf_(zf + 1.0f) + sigmoidf_(zi) * tanhf(zj);
    r.nh = tanhf(r.nc) * sigmoidf_(zo);
    return r;
}

__global__ void __launch_bounds__(TPB, 1) encoder_kernel(
    const int* __restrict__ en_input, const int* __restrict__ en_len,
    const float* __restrict__ b1g)
{
    extern __shared__ float sm[];
    float* ws0 = sm;                 // 512*16
    float* ws1 = sm + 512 * 16;      // 1024*16
    float* xs  = sm + 1536 * 16;     // 2 * XBUF

    const int cta = blockIdx.x, tid = threadIdx.x;
    const int m = tid >> 3, cp = tid & 7;
    const int ul = cp >> 1, gp = cp & 1;
    const int unit = cta * 4 + ul;
    const int qb = (tid & 7) * 4;

    // preload weights (slabs are [k][16] per CTA)
    {
        const float4* w0g = (const float4*)(g_Wr) + (size_t)cta * (512 * 4);
        float4* s0 = (float4*)ws0;
        for (int i = tid; i < 512 * 4; i += TPB) s0[i] = w0g[i];
        const float4* w1g = (const float4*)(g_Wr + (size_t)512 * 2048) + (size_t)cta * (1024 * 4);
        float4* s1 = (float4*)ws1;
        for (int i = tid; i < 1024 * 4; i += TPB) s1[i] = w1g[i];
    }
    float2 b1 = make_float2(b1g[(2 * gp + 0) * 512 + unit], b1g[(2 * gp + 1) * 512 + unit]);
    const int mylen = en_len[m];
    const float2* w0b = reinterpret_cast<const float2*>(ws0) + cp;
    const float2* w1b = reinterpret_cast<const float2*>(ws1) + cp;

    float c0 = 0.f, c1v = 0.f, h0r = 0.f, h1r = 0.f;
    __syncthreads();

    for (int t = 0; t < 256; ++t) {
        const float* h0prev = g_h0 + ((t + 1) & 1) * (64 * 512);
        float*       h0cur  = g_h0 + (t & 1) * (64 * 512);
        const float* h1prev = g_h1 + ((t + 1) & 1) * (64 * 512);
        float*       h1cur  = g_h1 + (t & 1) * (64 * 512);

        int tok = en_input[m * 256 + t];
        float2 ez = *reinterpret_cast<const float2*>(
            g_embz_enc + (size_t)tok * 2048 + cta * 16 + cp * 2);

        // ---- layer 0: K=512 (h0prev), 4 chunks of 128 ----
        float2 acc = make_float2(0.f, 0.f);
        {
            float4 v[4];
            load4cg(h0prev, m, qb, v);        // note: qb covers quads 0..31 via j loop? no: qb..qb+3
            fill_x(xs, m, qb, v);
            int buf = 0;
            for (int ch = 0; ch < 4; ++ch) {
                float4 nv[4];
                if (ch + 1 < 4) load4cg(h0prev + (ch + 1) * 128, m, qb, nv);
                __syncthreads();
                compute_chunk(xs + buf * XBUF + m * XSTF, w0b + ch * 1024, acc);
                if (ch + 1 < 4) fill_x(xs + (buf ^ 1) * XBUF, m, qb, nv);
                buf ^= 1;
            }
        }
        acc.x += ez.x; acc.y += ez.y;
        {
            bool valid = t < mylen;
            GateOut g = lstm_gates(acc, gp, c0);
            if (valid) { c0 = g.nc; h0r = g.nh; }
            if (gp == 0) h0cur[m * 512 + unit] = h0r;
        }
        grid_bar((unsigned)(t + 1) * NCTA);

        // ---- layer 1: K=1024 (h0cur | h1prev), 8 chunks of 128 ----
        acc = make_float2(0.f, 0.f);
        {
            float4 v[4];
            load4cg(h0cur, m, qb, v);
            fill_x(xs, m, qb, v);
            int buf = 0;
            for (int ch = 0; ch < 8; ++ch) {
                float4 nv[4];
                if (ch + 1 < 8) {
                    int cn = ch + 1;
                    const float* hp = (cn < 4) ? (h0cur + cn * 128) : (h1prev + (cn - 4) * 128);
                    load4cg(hp, m, qb, nv);
                }
                __syncthreads();
                compute_chunk(xs + buf * XBUF + m * XSTF, w1b + ch * 1024, acc);
                if (ch + 1 < 8) fill_x(xs + (buf ^ 1) * XBUF, m, qb, nv);
                buf ^= 1;
            }
        }
        __syncthreads();   // protect xs before next phase's prologue STS
        acc.x += b1.x; acc.y += b1.y;
        {
            bool valid = t < mylen;
            GateOut g = lstm_gates(acc, gp, c1v);
            if (valid) { c1v = g.nc; h1r = g.nh; }
            if (gp == 0) {
                if (valid) g_en_last[m * 512 + unit] = h1r;
                h1cur[m * 512 + unit] = h1r;
            }
        }
    }
    if (gp == 0) {
        g_c0[m * 512 + unit] = c0;
        g_c1[m * 512 + unit] = c1v;
    }
}

__global__ void __launch_bounds__(TPB, 1) decoder_kernel(
    const int* __restrict__ dec_input, const int* __restrict__ dec_len,
    const float* __restrict__ b1g)
{
    extern __shared__ float sm[];
    float* ws0 = sm;                 // 512*16
    float* ws1 = sm + 512 * 16;      // 1024*16
    float* xs  = sm + 1536 * 16;

    const int cta = blockIdx.x, tid = threadIdx.x;
    const int m = tid >> 3, cp = tid & 7;
    const int ul = cp >> 1, gp = cp & 1;
    const int unit = cta * 4 + ul;
    const int qb = (tid & 7) * 4;

    {
        const float4* w0g = (const float4*)(g_Wr + (size_t)1536 * 2048) + (size_t)cta * (512 * 4);
        float4* s0 = (float4*)ws0;
        for (int i = tid; i < 512 * 4; i += TPB) s0[i] = w0g[i];
        const float4* w1g = (const float4*)(g_Wr + (size_t)2048 * 2048) + (size_t)cta * (1024 * 4);
        float4* s1 = (float4*)ws1;
        for (int i = tid; i < 1024 * 4; i += TPB) s1[i] = w1g[i];
    }
    float2 b1 = make_float2(b1g[(2 * gp + 0) * 512 + unit], b1g[(2 * gp + 1) * 512 + unit]);
    const int mylen = dec_len[m];
    float2 el = *reinterpret_cast<const float2*>(
        g_enlz + (size_t)m * 2048 + cta * 16 + cp * 2);

    const float2* w0b = reinterpret_cast<const float2*>(ws0) + cp;
    const float2* w1b = reinterpret_cast<const float2*>(ws1) + cp;

    float c0 = g_c0[m * 512 + unit];
    float c1v = g_c1[m * 512 + unit];
    float h0r = g_h0[64 * 512 + m * 512 + unit];   // encoder t=255 wrote buffer 1
    float h1r = g_h1[64 * 512 + m * 512 + unit];
    __syncthreads();

    for (int t = 0; t < 256; ++t) {
        const float* h0prev = g_h0 + ((t + 1) & 1) * (64 * 512);
        float*       h0cur  = g_h0 + (t & 1) * (64 * 512);
        const float* h1prev = g_h1 + ((t + 1) & 1) * (64 * 512);
        float*       h1cur  = g_h1 + (t & 1) * (64 * 512);

        int tok = dec_input[m * 256 + t];
        float2 ez = *reinterpret_cast<const float2*>(
            g_embz_dec + (size_t)tok * 2048 + cta * 16 + cp * 2);

        // ---- layer 0: K=512 (h0prev), 4 chunks of 128 ----
        float2 acc = make_float2(0.f, 0.f);
        {
            float4 v[4];
            load4cg(h0prev, m, qb, v);
            fill_x(xs, m, qb, v);
            int buf = 0;
            for (int ch = 0; ch < 4; ++ch) {
                float4 nv[4];
                if (ch + 1 < 4) load4cg(h0prev + (ch + 1) * 128, m, qb, nv);
                __syncthreads();
                compute_chunk(xs + buf * XBUF + m * XSTF, w0b + ch * 1024, acc);
                if (ch + 1 < 4) fill_x(xs + (buf ^ 1) * XBUF, m, qb, nv);
                buf ^= 1;
            }
        }
        acc.x += ez.x + el.x; acc.y += ez.y + el.y;
        {
            bool valid = t < mylen;
            GateOut g = lstm_gates(acc, gp, c0);
            if (valid) { c0 = g.nc; h0r = g.nh; }
            if (gp == 0) h0cur[m * 512 + unit] = h0r;
        }
        grid_bar((unsigned)(256 + t + 1) * NCTA);

        // ---- layer 1: K=1024, 8 chunks ----
        acc = make_float2(0.f, 0.f);
        {
            float4 v[4];
            load4cg(h0cur, m, qb, v);
            fill_x(xs, m, qb, v);
            int buf = 0;
            for (int ch = 0; ch < 8; ++ch) {
                float4 nv[4];
                if (ch + 1 < 8) {
                    int cn = ch + 1;
                    const float* hp = (cn < 4) ? (h0cur + cn * 128) : (h1prev + (cn - 4) * 128);
                    load4cg(hp, m, qb, nv);
                }
                __syncthreads();
                compute_chunk(xs + buf * XBUF + m * XSTF, w1b + ch * 1024, acc);
                if (ch + 1 < 8) fill_x(xs + (buf ^ 1) * XBUF, m, qb, nv);
                buf ^= 1;
            }
        }
        __syncthreads();
        acc.x += b1.x; acc.y += b1.y;
        {
            bool valid = t < mylen;
            GateOut g = lstm_gates(acc, gp, c1v);
            if (valid) { c1v = g.nc; h1r = g.nh; }
            if (gp == 0) {
                h1cur[m * 512 + unit] = h1r;
                g_dec_out[((size_t)m * 256 + t) * 512 + unit] = valid ? h1r : 0.f;
            }
        }
    }
}

// ---------------- projection: [16384,512] @ [512,128] + bias ----------------
__global__ void __launch_bounds__(256, 1) proj_kernel(
    const float* __restrict__ projW, const float* __restrict__ projb,
    float* __restrict__ out)
{
    const int row0 = blockIdx.x * 128;
    __shared__ __align__(16) float As[128][33];
    __shared__ __align__(16) float Ws[32][128];
    const int tid = threadIdx.x;
    const int tc = tid & 31, rg = tid >> 5;

    float4 acc[16];
#pragma unroll
    for (int i = 0; i < 16; i++) acc[i] = make_float4(0.f, 0.f, 0.f, 0.f);

    for (int k0 = 0; k0 < 512; k0 += 32) {
        for (int e = tid; e < 128 * 32; e += 256) {
            int r = e >> 5, kk = e & 31;
            As[r][kk] = g_dec_out[(size_t)(row0 + r) * 512 + k0 + kk];
        }
        for (int e = tid; e < 32 * 128; e += 256) {
            int kk = e >> 7, c = e & 127;
            Ws[kk][c] = projW[(size_t)(k0 + kk) * 128 + c];
        }
        __syncthreads();
#pragma unroll
        for (int kk = 0; kk < 32; kk++) {
            float4 w = *reinterpret_cast<const float4*>(&Ws[kk][tc * 4]);
#pragma unroll
            for (int r = 0; r < 16; r++) {
                float a = As[rg * 16 + r][kk];
                acc[r].x = fmaf(a, w.x, acc[r].x);
                acc[r].y = fmaf(a, w.y, acc[r].y);
                acc[r].z = fmaf(a, w.z, acc[r].z);
                acc[r].w = fmaf(a, w.w, acc[r].w);
            }
        }
        __syncthreads();
    }
    float4 pb = *reinterpret_cast<const float4*>(&projb[tc * 4]);
#pragma unroll
    for (int r = 0; r < 16; r++) {
        int row = row0 + rg * 16 + r;
        float4 v = make_float4(acc[r].x + pb.x, acc[r].y + pb.y,
                               acc[r].z + pb.z, acc[r].w + pb.w);
        *reinterpret_cast<float4*>(&out[(size_t)row * 128 + tc * 4]) = v;
    }
}

// ---------------- launch ----------------
#define SEQ_SMEM ((1536 * 16 + 2 * XBUF) * 4)

extern "C" void kernel_launch(void* const* d_in, const int* in_sizes, int n_in,
                              void* d_out, int out_size) {
    const int*   en_input  = (const int*)d_in[0];
    const int*   en_len    = (const int*)d_in[1];
    const int*   dec_input = (const int*)d_in[2];
    const int*   dec_len   = (const int*)d_in[3];
    const float* embed     = (const float*)d_in[4];
    const float* encW0     = (const float*)d_in[5];
    const float* encb0     = (const float*)d_in[6];
    const float* encW1     = (const float*)d_in[7];
    const float* encb1     = (const float*)d_in[8];
    const float* decW0     = (const float*)d_in[9];
    const float* decb0     = (const float*)d_in[10];
    const float* decW1     = (const float*)d_in[11];
    const float* decb1     = (const float*)d_in[12];
    const float* projW     = (const float*)d_in[13];
    const float* projb     = (const float*)d_in[14];
    float* out = (float*)d_out;

    float* embz_enc; cudaGetSymbolAddress((void**)&embz_enc, g_embz_enc);
    float* embz_dec; cudaGetSymbolAddress((void**)&embz_dec, g_embz_dec);
    float* enlz;     cudaGetSymbolAddress((void**)&enlz, g_enlz);
    float* en_last;  cudaGetSymbolAddress((void**)&en_last, g_en_last);

    cudaFuncSetAttribute(encoder_kernel, cudaFuncAttributeMaxDynamicSharedMemorySize, SEQ_SMEM);
    cudaFuncSetAttribute(decoder_kernel, cudaFuncAttributeMaxDynamicSharedMemorySize, SEQ_SMEM);

    init_kernel<<<128, 256>>>();
    // recurrent-weight slabs (h-parts only)
    reorder_kernel<<<512, 256>>>(encW0 + (size_t)256 * 2048, (size_t)0,           512);
    reorder_kernel<<<512, 256>>>(encW1,                      (size_t)512  * 2048, 1024);
    reorder_kernel<<<512, 256>>>(decW0 + (size_t)768 * 2048, (size_t)1536 * 2048, 512);
    reorder_kernel<<<512, 256>>>(decW1,                      (size_t)2048 * 2048, 1024);
    // token tables (fold layer-0 biases)
    gemm_pre<<<16, 256>>>(embed, 128, 256, encW0, encb0, embz_enc);
    gemm_pre<<<16, 256>>>(embed, 128, 256, decW0, decb0, embz_dec);

    encoder_kernel<<<NCTA, TPB, SEQ_SMEM>>>(en_input, en_len, encb1);

    // en_last @ decW0[256:768] (constant over all decoder steps)
    gemm_pre<<<16, 256>>>(en_last, 64, 512, decW0 + (size_t)256 * 2048, (const float*)nullptr, enlz);

    decoder_kernel<<<NCTA, TPB, SEQ_SMEM>>>(dec_input, dec_len, decb1);
    proj_kernel<<<128, 256>>>(projW, projb, out);
}